// round 3
// baseline (speedup 1.0000x reference)
#include <cuda_runtime.h>

// AllZeroDigitalFilter: time-varying FIR, 50 taps, frame period 80.
// y[b,t] = sum_{j=0..49} x[b, t+j-49] * h[b,t,j]
// h[t=n*80+p][j] = (1-p/80)*bf[n][j] + (p/80)*bf[min(n+1,N-1)][j], bf[n][j]=b[n][49-j]
// Split: y = a0 + w*a1, a0 = sum x*cL, a1 = sum x*(cR-cL).
// (a0,a1) packed in one 64-bit reg pair, advanced with fma.rn.f32x2 (FFMA2),
// coefficients stored interleaved as float2 so one LDS.64 yields the packed operand.

#define TAPS       50
#define FP         80
#define FPB        20          // frames per block
#define THREADS    160         // 8 threads/frame, exactly 5 warps
#define KOUT       10          // outputs per thread (8*10 = 80 = FP)
#define XWIN       1650        // x window: [t0-49, t0+1601)
#define PAD(i)     ((i) + (i) / 10)   // stride-11 padding (11 coprime 32): conflict-free

typedef unsigned long long u64;

__device__ __forceinline__ u64 pack2(float a, float b) {
    u64 r;
    asm("mov.b64 %0, {%1, %2};" : "=l"(r) : "f"(a), "f"(b));
    return r;
}
__device__ __forceinline__ void unpack2(u64 v, float& a, float& b) {
    asm("mov.b64 {%0, %1}, %2;" : "=f"(a), "=f"(b) : "l"(v));
}
__device__ __forceinline__ u64 ffma2(u64 a, u64 b, u64 c) {
    u64 d;
    asm("fma.rn.f32x2 %0, %1, %2, %3;" : "=l"(d) : "l"(a), "l"(b), "l"(c));
    return d;
}

__global__ __launch_bounds__(THREADS, 6)
void azdf_kernel(const float* __restrict__ x,
                 const float* __restrict__ b,
                 float* __restrict__ y,
                 int T, int Nf)
{
    __shared__ float  sx[PAD(XWIN - 1) + 1];   // padded x window (stride 11 per 10)
    __shared__ float2 sC[FPB * TAPS];          // (cL, cR-cL) interleaved

    const int bb = blockIdx.y;
    const int n0 = blockIdx.x * FPB;
    const int t0 = n0 * FP;

    const float* xb  = x + (long long)bb * T;
    const float* bbp = b + (long long)bb * Nf * TAPS;

    // ---- stage x window (padded) ----
    for (int i = threadIdx.x; i < XWIN; i += THREADS) {
        int g = t0 - (TAPS - 1) + i;
        float v = (g >= 0 && g < T) ? xb[g] : 0.0f;
        sx[PAD(i)] = v;
    }

    // ---- stage coefficients: flip + diff, interleaved float2 ----
    for (int idx = threadIdx.x; idx < FPB * TAPS; idx += THREADS) {
        int r = idx / TAPS;
        int j = idx - r * TAPS;
        int n  = n0 + r;
        int n1 = min(n + 1, Nf - 1);
        float l  = bbp[n  * TAPS + (TAPS - 1 - j)];
        float rr = bbp[n1 * TAPS + (TAPS - 1 - j)];
        sC[idx] = make_float2(l, rr - l);
    }
    __syncthreads();

    // ---- per-thread: 10 consecutive outputs within one frame ----
    const int f  = threadIdx.x >> 3;          // frame within block (8 threads/frame)
    const int q  = threadIdx.x & 7;           // 10-output group within frame
    const int lt = 10 * threadIdx.x;          // == f*80 + q*10, multiple of 10

    // lt % 10 == 0  =>  PAD(lt + c) = PAD(lt) + PAD(c); PAD(c) folds to a constant.
    const float* sxp = sx + PAD(lt);          // = sx + 11*threadIdx.x
    const u64*   cp  = (const u64*)(sC + f * TAPS);

    u64 acc[KOUT];
    u64 xw[KOUT];
    #pragma unroll
    for (int k = 0; k < KOUT; ++k) {
        acc[k] = 0ULL;
        float v = sxp[PAD(k)];                // PAD(k)=k for k<10
        xw[k] = pack2(v, v);
    }

    #pragma unroll
    for (int j = 0; j < TAPS; ++j) {
        u64 c2 = cp[j];                       // LDS.64: packed (cL, cD)
        #pragma unroll
        for (int k = 0; k < KOUT; ++k)
            acc[k] = ffma2(xw[k], c2, acc[k]);
        #pragma unroll
        for (int k = 0; k < KOUT - 1; ++k) xw[k] = xw[k + 1];  // renamed (full unroll)
        float v = sxp[PAD(j + KOUT)];         // compile-time offset
        xw[KOUT - 1] = pack2(v, v);
    }

    // ---- interpolate + store ----
    float out[KOUT];
    const float p0 = (float)(q * KOUT);
    #pragma unroll
    for (int k = 0; k < KOUT; ++k) {
        float a0, a1;
        unpack2(acc[k], a0, a1);
        float w = (p0 + (float)k) * (1.0f / (float)FP);
        out[k] = fmaf(w, a1, a0);
    }
    float* yp = y + (long long)bb * T + t0 + lt;   // 8-byte aligned (lt*4 = 40*tid)
    float2* yp2 = (float2*)yp;
    #pragma unroll
    for (int k = 0; k < KOUT / 2; ++k)
        yp2[k] = make_float2(out[2 * k], out[2 * k + 1]);
}

extern "C" void kernel_launch(void* const* d_in, const int* in_sizes, int n_in,
                              void* d_out, int out_size)
{
    const float* x = (const float*)d_in[0];   // (B, T) float32
    const float* b = (const float*)d_in[1];   // (B, N, 50) float32
    float* y = (float*)d_out;                 // (B, T) float32

    const int Nf = 3000;
    const int T  = Nf * FP;                   // 240000
    const int B  = in_sizes[0] / T;           // 8

    dim3 grid(Nf / FPB, B);                   // (150, 8)
    azdf_kernel<<<grid, THREADS>>>(x, b, y, T, Nf);
}

// round 5
// speedup vs baseline: 1.4549x; 1.4549x over previous
#include <cuda_runtime.h>

// AllZeroDigitalFilter: time-varying FIR, 50 taps, frame period 80.
// y[b,t] = sum_{j=0..49} x[b, t+j-49] * h[b,t,j]
// h[t=n*80+p][j] = (1-p/80)*bf[n][j] + (p/80)*bf[min(n+1,N-1)][j], bf[n][j]=b[n][49-j]
// Split: y = a0 + w*a1, a0 = sum x*cL, a1 = sum x*(cR-cL).
// (a0,a1) packed in a 64-bit pair, advanced with fma.rn.f32x2 (FFMA2).
// Coefficients stored interleaved (cL,cD) -> one LDS.64 per tap (warp broadcast).
// x stored duplicated (v,v) -> one LDS.64 per tap, odd float2 stride = conflict-free.

#define TAPS     50
#define FP       80
#define FPB      10            // frames per block
#define THREADS  160           // 16 threads/frame, exactly 5 warps
#define KOUT     5             // outputs per thread (16*5 = 80 = FP)
#define XWIN     (FPB * FP + TAPS)   // 850 samples: [t0-49, t0+801)

typedef unsigned long long u64;

__device__ __forceinline__ void unpack2(u64 v, float& a, float& b) {
    asm("mov.b64 {%0, %1}, %2;" : "=f"(a), "=f"(b) : "l"(v));
}
__device__ __forceinline__ u64 ffma2(u64 a, u64 b, u64 c) {
    u64 d;
    asm("fma.rn.f32x2 %0, %1, %2, %3;" : "=l"(d) : "l"(a), "l"(b), "l"(c));
    return d;
}

__global__ __launch_bounds__(THREADS, 10)
void azdf_kernel(const float* __restrict__ x,
                 const float* __restrict__ b,
                 float* __restrict__ y,
                 int T, int Nf)
{
    __shared__ float2 sx2[XWIN];          // (v, v) duplicated samples, 6.8 KB
    __shared__ float2 sC[FPB * TAPS];     // (cL, cR-cL) interleaved, 4 KB

    const int bb = blockIdx.y;
    const int n0 = blockIdx.x * FPB;
    const int t0 = n0 * FP;

    const float* xb  = x + (long long)bb * T;
    const float* bbp = b + (long long)bb * Nf * TAPS;

    // ---- stage x window, duplicated ----
    for (int i = threadIdx.x; i < XWIN; i += THREADS) {
        int g = t0 - (TAPS - 1) + i;
        float v = (g >= 0 && g < T) ? xb[g] : 0.0f;
        sx2[i] = make_float2(v, v);
    }

    // ---- stage coefficients: flip + diff, interleaved ----
    for (int idx = threadIdx.x; idx < FPB * TAPS; idx += THREADS) {
        int r = idx / TAPS;
        int j = idx - r * TAPS;
        int n  = n0 + r;
        int n1 = min(n + 1, Nf - 1);
        float l  = bbp[n  * TAPS + (TAPS - 1 - j)];
        float rr = bbp[n1 * TAPS + (TAPS - 1 - j)];
        sC[idx] = make_float2(l, rr - l);
    }
    __syncthreads();

    // ---- per-thread: 5 consecutive outputs within one frame ----
    const int f  = threadIdx.x >> 4;      // frame within block (16 threads/frame)
    const int q  = threadIdx.x & 15;      // 5-output group within frame
    const int lt = 5 * threadIdx.x;       // == f*80 + q*5

    const u64* xp = (const u64*)sx2 + lt; // per-thread stride 5 float2 (odd): conflict-free
    const u64* cp = (const u64*)(sC + f * TAPS);

    u64 acc[KOUT];
    u64 xw[KOUT];
    #pragma unroll
    for (int k = 0; k < KOUT; ++k) {
        acc[k] = 0ULL;
        xw[k]  = xp[k];
    }

    #pragma unroll
    for (int j = 0; j < TAPS; ++j) {
        u64 c2 = cp[j];                   // LDS.64 broadcast: packed (cL, cD)
        #pragma unroll
        for (int k = 0; k < KOUT; ++k)
            acc[k] = ffma2(xw[k], c2, acc[k]);
        #pragma unroll
        for (int k = 0; k < KOUT - 1; ++k) xw[k] = xw[k + 1];   // renamed (full unroll)
        xw[KOUT - 1] = xp[j + KOUT];      // LDS.64, compile-time offset
    }

    // ---- interpolate + store ----
    const float p0 = (float)(q * KOUT);
    float* yp = y + (long long)bb * T + t0 + lt;
    #pragma unroll
    for (int k = 0; k < KOUT; ++k) {
        float a0, a1;
        unpack2(acc[k], a0, a1);
        float w = (p0 + (float)k) * (1.0f / (float)FP);
        yp[k] = fmaf(w, a1, a0);
    }
}

extern "C" void kernel_launch(void* const* d_in, const int* in_sizes, int n_in,
                              void* d_out, int out_size)
{
    const float* x = (const float*)d_in[0];   // (B, T) float32
    const float* b = (const float*)d_in[1];   // (B, N, 50) float32
    float* y = (float*)d_out;                 // (B, T) float32

    const int Nf = 3000;
    const int T  = Nf * FP;                   // 240000
    const int B  = in_sizes[0] / T;           // 8

    dim3 grid(Nf / FPB, B);                   // (300, 8) = 2400 blocks
    azdf_kernel<<<grid, THREADS>>>(x, b, y, T, Nf);
}